// round 10
// baseline (speedup 1.0000x reference)
#include <cuda_runtime.h>
#include <cstdint>

// Scene splatting via fused tile-gather (single kernel):
// out[c, y+r, x+q] += patches[n, c, r, q]; frame C=5,H=4096,W=4096; N=2000 64x64 patches.
// One CTA per 64x64 spatial tile. The CTA scans all positions (L2-resident, 16KB),
// builds its overlap list in shared memory, then for each of the 5 channels
// accumulates its tile in registers and writes it exactly once with float4 stores.
// No zero pass, no output atomics, no global scratch.

static constexpr int C  = 5;
static constexpr int H  = 4096;
static constexpr int W  = 4096;
static constexpr int PH = 64;
static constexpr int PW = 64;
static constexpr int N_SRC = 2000;

static constexpr int TILE    = 64;
static constexpr int TILES_X = W / TILE;   // 64
static constexpr int NTILES  = (H / TILE) * TILES_X;  // 4096
static constexpr int CAP     = 512;        // per-tile overlap list capacity (mean ~2)

__global__ __launch_bounds__(256) void scene_kernel(
    const float* __restrict__ patches,    // [N, C, PH, PW]
    const int*   __restrict__ positions,  // [N, 2] (y, x)
    float* __restrict__ out)              // [C, H, W]
{
    __shared__ int s_cnt;
    __shared__ int s_n[CAP];
    __shared__ int s_y[CAP];
    __shared__ int s_x[CAP];

    const int tile = blockIdx.x;          // 0 .. 4095
    const int TY   = (tile >> 6) * TILE;
    const int TX   = (tile & 63) * TILE;
    const int tid  = threadIdx.x;

    // ---- Phase 1: cooperative scan of all source positions ----
    if (tid == 0) s_cnt = 0;
    __syncthreads();

    const int2* __restrict__ pos2 = (const int2*)positions;
    for (int n = tid; n < N_SRC; n += 256) {
        const int2 yx = pos2[n];
        const int y = yx.x;
        const int x = yx.y;
        if (y < TY + TILE && y + PH > TY && x < TX + TILE && x + PW > TX) {
            const int s = atomicAdd(&s_cnt, 1);
            if (s < CAP) { s_n[s] = n; s_y[s] = y; s_x[s] = x; }
        }
    }
    __syncthreads();

    int cnt = s_cnt;
    if (cnt > CAP) cnt = CAP;

    // ---- Phase 2: per-channel register accumulation + vectorized write ----
    // Thread layout: g = tid & 15 -> columns [4g, 4g+4); r0 = tid >> 4 -> rows
    // r0 + 16k, k = 0..3. Each thread owns 16 pixels per channel, written as
    // 4x STG.128 (16B-aligned: TX is a multiple of 64 floats).
    const int g  = tid & 15;
    const int r0 = tid >> 4;
    const int colbase = 4 * g;

    for (int c = 0; c < C; c++) {
        float acc[4][4];
        #pragma unroll
        for (int k = 0; k < 4; k++)
            #pragma unroll
            for (int j = 0; j < 4; j++)
                acc[k][j] = 0.0f;

        for (int i = 0; i < cnt; i++) {
            const int n = s_n[i];
            const int y = s_y[i];
            const int x = s_x[i];

            const int pq0 = TX + colbase - x;     // patch col of j=0
            if (pq0 + 3 >= 0 && pq0 < PW) {
                const float* __restrict__ p =
                    patches + ((size_t)(n * C + c)) * (PH * PW);
                const int prbase = TY + r0 - y;   // patch row for k=0
                #pragma unroll
                for (int k = 0; k < 4; k++) {
                    const int pr = prbase + 16 * k;
                    if (pr >= 0 && pr < PH) {
                        const float* __restrict__ row = p + pr * PW;
                        #pragma unroll
                        for (int j = 0; j < 4; j++) {
                            const int pq = pq0 + j;
                            if (pq >= 0 && pq < PW) {
                                acc[k][j] += __ldg(row + pq);
                            }
                        }
                    }
                }
            }
        }

        float* __restrict__ ob =
            out + ((size_t)c * H + TY) * W + TX + colbase;
        #pragma unroll
        for (int k = 0; k < 4; k++) {
            const float4 v = make_float4(acc[k][0], acc[k][1],
                                         acc[k][2], acc[k][3]);
            __stcs((float4*)(ob + (size_t)(r0 + 16 * k) * W), v);
        }
    }
}

extern "C" void kernel_launch(void* const* d_in, const int* in_sizes, int n_in,
                              void* d_out, int out_size) {
    const float* patches   = (const float*)d_in[0];
    const int*   positions = (const int*)d_in[1];
    float*       out       = (float*)d_out;

    scene_kernel<<<NTILES, 256>>>(patches, positions, out);
}

// round 11
// speedup vs baseline: 1.1482x; 1.1482x over previous
#include <cuda_runtime.h>
#include <cstdint>

// Scene splatting via tile-binned gather, issue-lean version.
// out[c, y+r, x+q] += patches[n, c, r, q]; frame C=5,H=4096,W=4096; N=2000 64x64 patches.
// Pass 1 (memset): reset per-tile counters.
// Pass 2 (bin):    bin patches into the <=4 tiles they overlap (stores n and packed y,x).
// Pass 3 (gather): one CTA per (tile, channel); thread owns 4 float4 rows in registers,
//                  all heavy-loop addresses are [Rbase + immediate].

static constexpr int C  = 5;
static constexpr int H  = 4096;
static constexpr int W  = 4096;
static constexpr int PH = 64;
static constexpr int PW = 64;
static constexpr int N_SRC = 2000;

static constexpr int TILE    = 64;
static constexpr int TILES_X = W / TILE;             // 64
static constexpr int NTILES  = (H / TILE) * TILES_X; // 4096
static constexpr int MAXP    = 64;                   // per-tile capacity (mean ~2)

__device__ int g_cnt[NTILES];
__device__ int g_n [NTILES][MAXP];
__device__ int g_yx[NTILES][MAXP];   // (y << 16) | x

// ---------------------------------------------------------------------------
// bin: each patch registers itself in the tiles it overlaps.
// ---------------------------------------------------------------------------
__global__ void bin_kernel(const int* __restrict__ positions) {
    const int n = blockIdx.x * blockDim.x + threadIdx.x;
    if (n >= N_SRC) return;
    const int y = positions[2 * n + 0];
    const int x = positions[2 * n + 1];
    const int packed = (y << 16) | x;
    const int ty0 = y >> 6, ty1 = (y + PH - 1) >> 6;
    const int tx0 = x >> 6, tx1 = (x + PW - 1) >> 6;
    for (int ty = ty0; ty <= ty1; ty++) {
        for (int tx = tx0; tx <= tx1; tx++) {
            const int t = ty * TILES_X + tx;
            const int slot = atomicAdd(&g_cnt[t], 1);
            if (slot < MAXP) { g_n[t][slot] = n; g_yx[t][slot] = packed; }
        }
    }
}

// ---------------------------------------------------------------------------
// gather: CTA = (spatial tile, channel). 256 threads.
// Thread (g = tid&15, r0 = tid>>4) owns cols [4g,4g+4) of rows r0+16k, k=0..3.
// ---------------------------------------------------------------------------
__global__ __launch_bounds__(256) void gather_kernel(
    const float* __restrict__ patches,   // [N, C, PH, PW]
    float* __restrict__ out)             // [C, H, W]
{
    const int tile = blockIdx.x;
    const int c    = blockIdx.y;
    const int TY   = (tile >> 6) * TILE;
    const int TX   = (tile & 63) * TILE;

    const int tid     = threadIdx.x;
    const int g       = tid & 15;
    const int r0      = tid >> 4;
    const int colbase = g << 2;

    float acc[4][4];
    #pragma unroll
    for (int k = 0; k < 4; k++)
        #pragma unroll
        for (int j = 0; j < 4; j++) acc[k][j] = 0.0f;

    int cnt = g_cnt[tile];
    if (cnt > MAXP) cnt = MAXP;

    const int*   ln = g_n[tile];
    const int*   lp = g_yx[tile];
    const float* pc = patches + c * (PH * PW);   // channel base

    for (int i = 0; i < cnt; i++) {
        const int n      = __ldg(ln + i);
        const int packed = __ldg(lp + i);
        const int y = packed >> 16;
        const int x = packed & 0xffff;

        const int pq0 = TX + colbase - x;        // patch col of j=0
        if (pq0 > -4 && pq0 < PW) {
            const int prbase = TY + r0 - y;      // patch row for k=0
            // base pointer may be out of range; only dereferenced under predicate
            const float* pb = pc + n * (C * PH * PW) + prbase * PW + pq0;
            #pragma unroll
            for (int k = 0; k < 4; k++) {
                if ((unsigned)(prbase + 16 * k) < (unsigned)PH) {
                    #pragma unroll
                    for (int j = 0; j < 4; j++) {
                        if ((unsigned)(pq0 + j) < (unsigned)PW) {
                            acc[k][j] += __ldg(pb + k * (16 * PW) + j);
                        }
                    }
                }
            }
        }
    }

    // Vectorized, immediate-offset stores (tile origin is 256B aligned).
    float4* ob4 = (float4*)(out + ((size_t)c * H + TY) * W + TX)
                  + r0 * (W / 4) + g;
    #pragma unroll
    for (int k = 0; k < 4; k++) {
        const float4 v = make_float4(acc[k][0], acc[k][1], acc[k][2], acc[k][3]);
        __stcs(ob4 + k * 16 * (W / 4), v);
    }
}

extern "C" void kernel_launch(void* const* d_in, const int* in_sizes, int n_in,
                              void* d_out, int out_size) {
    const float* patches   = (const float*)d_in[0];
    const int*   positions = (const int*)d_in[1];
    float*       out       = (float*)d_out;

    void* cnt_addr = nullptr;
    cudaGetSymbolAddress(&cnt_addr, g_cnt);
    cudaMemsetAsync(cnt_addr, 0, NTILES * sizeof(int));

    bin_kernel<<<(N_SRC + 255) / 256, 256>>>(positions);

    dim3 grid(NTILES, C);
    gather_kernel<<<grid, 256>>>(patches, out);
}